// round 13
// baseline (speedup 1.0000x reference)
#include <cuda_runtime.h>
#include <cstdint>

#define KK 64
#define BUFB 288   // padded u-buffer stride in bytes: 32 floats | 16B pad | 32 floats | 16B pad

__device__ __forceinline__ float fast_rcp(float x) {
    float r; asm("rcp.approx.f32 %0, %1;" : "=f"(r) : "f"(x)); return r;
}

__device__ __forceinline__ uint32_t smem_u32(const void* p) {
    uint32_t a;
    asm("{ .reg .u64 t; cvta.to.shared.u64 t, %1; cvt.u32.u64 %0, t; }"
        : "=r"(a) : "l"(p));
    return a;
}

// ONE BLOCK (2 warps, 64 threads) PER BATCH — R12 half-u split, with the step
// body rescheduled for latency: all 8 u-chunk LDS issued up front, PARTNER
// partial computed first so the shfl.xor(16) overlaps the own-output chain,
// 4-deep FMA chains (4 accumulators per output), and y prefetched through
// registers so no y LDS sits on the step path.
//   u_t = (u_{t-1} . M) * exp(emit_t)        (masked steps: u_t = u_{t-1})
//   every 8th step (unconditional): u *= 1/u[0], C += log(u[0])
//   log_Z = C + log(sum_j u_T[j])
__global__ __launch_bounds__(KK, 1) void crf_forward_kernel(
    const int* __restrict__ y, const float* __restrict__ em,
    const float* __restrict__ tr, int Tn, float negInvB,
    float* __restrict__ out)
{
    __shared__ __align__(128) float u_sh[2][BUFB / 4]; // [buf][padded states]
    __shared__ int y_sh[1024];                         // T = 1024
    __shared__ float red2[2];

    const int tid = threadIdx.x;
    const int w = tid >> 5;               // warp
    const int l = tid & 31;               // lane
    const int h = (l >> 4) & 1;           // which u-half this thread loads
    const int so = 2 * l + w;             // own output state
    const int sp = 2 * (l ^ 16) + w;      // partner's output state
    const int b = blockIdx.x;
    const int* yb = y + (size_t)b * Tn;
    const float* eb = em + (size_t)b * Tn * KK;

    // padded float index for state s: halves 16B apart
    auto pidx = [](int s) { return s + ((s >= 32) ? 4 : 0); };

    // M pairs over MY half of rows, for my output and my partner's output:
    //   MpO[k] = (exp(tr[32h+2k][so]), exp(tr[32h+2k+1][so])), k = 0..15
    unsigned long long MpO[16], MpP[16];
#pragma unroll
    for (int k = 0; k < 16; k++) {
        const int r0 = (32 * h + 2 * k) * KK;
        float o0 = __expf(tr[r0 + so]);
        float o1 = __expf(tr[r0 + KK + so]);
        float p0 = __expf(tr[r0 + sp]);
        float p1 = __expf(tr[r0 + KK + sp]);
        asm("mov.b64 %0, {%1, %2};" : "=l"(MpO[k]) : "f"(o0), "f"(o1));
        asm("mov.b64 %0, {%1, %2};" : "=l"(MpP[k]) : "f"(p0), "f"(p1));
    }

    // stage y row in shared (cooperative)
    for (int t = tid; t < Tn; t += KK) y_sh[t] = yb[t];

    // u0 = exp(emissions[b,0,:]); own value kept in a register too
    float uown = __expf(eb[so]);
    u_sh[0][pidx(so)] = uown;
    float C = 0.f;
    __syncthreads();

    const uint32_t ubase = smem_u32(&u_sh[0][0]);
    const uint32_t uld0  = ubase + (uint32_t)(h * 144);      // my half base
    const uint32_t ust   = ubase + (uint32_t)(pidx(so) << 2);
    const float* ep = eb + so;

    // One recursion step. PSRC/RESC compile-time in the hot loop.
    // Shared loads/stores are asm volatile: prevents cross-step CSE of the
    // textually-identical unrolled bodies (the R4/R5 bug) and pins ordering.
    auto step = [&](float ecur, int yt, int psrc, bool resc) {
        float ex = __expf(ecur);
        float sc = 1.f;
        if (resc) {                       // unconditional rescale (valid always)
            float x0;
            asm volatile("ld.shared.f32 %0, [%1];"
                         : "=f"(x0) : "r"(ubase + (uint32_t)(psrc * BUFB)));
            sc = fast_rcp(x0);
            C += __logf(x0);
        }
        const float k = ex * sc;          // off the u-dependency chain
        const uint32_t ua = uld0 + (uint32_t)(psrc * BUFB);

        // 1) issue ALL chunk loads up front (pay LDS latency once, MLP)
        unsigned long long q[16];
#pragma unroll
        for (int i = 0; i < 8; i++) {
            asm volatile("ld.shared.v2.u64 {%0, %1}, [%2];"
                : "=l"(q[2 * i]), "=l"(q[2 * i + 1]) : "r"(ua + i * 16));
        }

        // 2) PARTNER partial first (4 accs, 4-deep) -> shfl issues early and
        //    its 26-cyc latency overlaps the own-output chain below.
        unsigned long long B0 = 0, B1 = 0, B2 = 0, B3 = 0;
#pragma unroll
        for (int i = 0; i < 4; i++) {
            asm("fma.rn.f32x2 %0, %1, %2, %0;" : "+l"(B0) : "l"(q[4 * i + 0]), "l"(MpP[4 * i + 0]));
            asm("fma.rn.f32x2 %0, %1, %2, %0;" : "+l"(B1) : "l"(q[4 * i + 1]), "l"(MpP[4 * i + 1]));
            asm("fma.rn.f32x2 %0, %1, %2, %0;" : "+l"(B2) : "l"(q[4 * i + 2]), "l"(MpP[4 * i + 2]));
            asm("fma.rn.f32x2 %0, %1, %2, %0;" : "+l"(B3) : "l"(q[4 * i + 3]), "l"(MpP[4 * i + 3]));
        }
        asm("add.rn.f32x2 %0, %0, %1;" : "+l"(B0) : "l"(B2));
        asm("add.rn.f32x2 %0, %0, %1;" : "+l"(B1) : "l"(B3));
        asm("add.rn.f32x2 %0, %0, %1;" : "+l"(B0) : "l"(B1));
        float blo, bhi;
        asm("mov.b64 {%0, %1}, %2;" : "=f"(blo), "=f"(bhi) : "l"(B0));
        float PB = blo + bhi;                               // my half, partner's out
        float PBr = __shfl_xor_sync(0xffffffffu, PB, 16);   // other half, my out

        // 3) OWN partial (4 accs, 4-deep) overlapping the shfl latency
        unsigned long long A0 = 0, A1 = 0, A2 = 0, A3 = 0;
#pragma unroll
        for (int i = 0; i < 4; i++) {
            asm("fma.rn.f32x2 %0, %1, %2, %0;" : "+l"(A0) : "l"(q[4 * i + 0]), "l"(MpO[4 * i + 0]));
            asm("fma.rn.f32x2 %0, %1, %2, %0;" : "+l"(A1) : "l"(q[4 * i + 1]), "l"(MpO[4 * i + 1]));
            asm("fma.rn.f32x2 %0, %1, %2, %0;" : "+l"(A2) : "l"(q[4 * i + 2]), "l"(MpO[4 * i + 2]));
            asm("fma.rn.f32x2 %0, %1, %2, %0;" : "+l"(A3) : "l"(q[4 * i + 3]), "l"(MpO[4 * i + 3]));
        }
        asm("add.rn.f32x2 %0, %0, %1;" : "+l"(A0) : "l"(A2));
        asm("add.rn.f32x2 %0, %0, %1;" : "+l"(A1) : "l"(A3));
        asm("add.rn.f32x2 %0, %0, %1;" : "+l"(A0) : "l"(A1));
        float alo, ahi;
        asm("mov.b64 {%0, %1}, %2;" : "=f"(alo), "=f"(ahi) : "l"(A0));
        float PA = alo + ahi;

        float dx = (PA + PBr) * k;
        // branchless commit (no BSSY/BSYNC in the hot loop)
        uown = (yt != 0) ? dx : uown * sc;
        asm volatile("st.shared.f32 [%0], %1;"
                     :: "r"(ust + (uint32_t)((psrc ^ 1) * BUFB)), "f"(uown));
        __syncthreads();
    };

    const int lim = Tn - 1;               // 1023
    auto eld = [&](int t) { return ep[(size_t)t * KK]; };

    // prefetch rows t .. t+7 (emissions AND y labels; no clamps: lim >= 8)
    float e0 = eld(1), e1 = eld(2), e2 = eld(3), e3 = eld(4);
    float e4 = eld(5), e5 = eld(6), e6 = eld(7), e7 = eld(8);
    int   y0 = y_sh[1], y1 = y_sh[2], y2 = y_sh[3], y3 = y_sh[4];
    int   y4 = y_sh[5], y5 = y_sh[6], y6 = y_sh[7], y7 = y_sh[8];

    int t = 1;
    // main loop: t ≡ 1 (mod 8); parity at entry always 0; rescale at t+7 (≡0 mod 8)
    for (; t + 15 <= lim; t += 8) {
        float n0 = eld(t + 8),  n1 = eld(t + 9),  n2 = eld(t + 10), n3 = eld(t + 11);
        float n4 = eld(t + 12), n5 = eld(t + 13), n6 = eld(t + 14), n7 = eld(t + 15);
        int   m0 = y_sh[t + 8],  m1 = y_sh[t + 9],  m2 = y_sh[t + 10], m3 = y_sh[t + 11];
        int   m4 = y_sh[t + 12], m5 = y_sh[t + 13], m6 = y_sh[t + 14], m7 = y_sh[t + 15];
        step(e0, y0, 0, false);
        step(e1, y1, 1, false);
        step(e2, y2, 0, false);
        step(e3, y3, 1, false);
        step(e4, y4, 0, false);
        step(e5, y5, 1, false);
        step(e6, y6, 0, false);
        step(e7, y7, 1, true);
        e0 = n0; e1 = n1; e2 = n2; e3 = n3;
        e4 = n4; e5 = n5; e6 = n6; e7 = n7;
        y0 = m0; y1 = m1; y2 = m2; y3 = m3;
        y4 = m4; y5 = m5; y6 = m6; y7 = m7;
    }

    // tail: runtime parity / rescale; shift-register prefetch with clamped loads
    int p = 0;                             // (t-1) is a multiple of 8 here
    for (; t <= lim; t++) {
        float nn = eld(min(t + 8, lim));
        int   mm = y_sh[min(t + 8, lim)];
        step(e0, y0, p, (t & 7) == 0);
        p ^= 1;
        e0 = e1; e1 = e2; e2 = e3; e3 = e4;
        e4 = e5; e5 = e6; e6 = e7; e7 = nn;
        y0 = y1; y1 = y2; y2 = y3; y3 = y4;
        y4 = y5; y5 = y6; y6 = y7; y7 = mm;
    }
    // final buffer parity: lim steps total from parity 0
    const int pf = lim & 1;

    // (last step ended with __syncthreads; u_sh[pf] is visible)

    // log_Z = C + log(sum u)   (redundant per-thread; identical result)
    float ssum = 0.f;
    {
        const float* up = &u_sh[pf][0];
#pragma unroll
        for (int c = 0; c < 16; c++) {
            const int fi = 4 * c + ((c >= 8) ? 4 : 0);   // padded layout
            float4 uu = *reinterpret_cast<const float4*>(up + fi);
            ssum += (uu.x + uu.y) + (uu.z + uu.w);
        }
    }
    float logz = C + __logf(ssum);

    // numerator: emission + transition scores along the gold path (masked)
    float num = 0.f;
    for (int tt = tid; tt < Tn; tt += KK) {
        int yt = y_sh[tt];
        if (yt != 0) {
            num += eb[(size_t)tt * KK + yt];
            if (tt > 0) num += tr[y_sh[tt - 1] * KK + yt];
        }
    }
#pragma unroll
    for (int o = 16; o > 0; o >>= 1) num += __shfl_xor_sync(0xffffffffu, num, o);
    if (l == 0) red2[w] = num;
    __syncthreads();
    if (tid == 0) {
        float ll = (red2[0] + red2[1]) - logz;
        atomicAdd(out, ll * negInvB);      // out pre-zeroed via memsetAsync
    }
}

extern "C" void kernel_launch(void* const* d_in, const int* in_sizes, int n_in,
                              void* d_out, int out_size)
{
    const int*   y  = (const int*)d_in[0];
    const float* em = (const float*)d_in[1];
    const float* tr = (const float*)d_in[2];

    const int Tn = 1024;                 // problem shape: B=256, T=1024, K=64
    const int B  = in_sizes[0] / Tn;

    cudaMemsetAsync(d_out, 0, sizeof(float));
    crf_forward_kernel<<<B, KK>>>(y, em, tr, Tn, -1.0f / (float)B,
                                  (float*)d_out);
}

// round 14
// speedup vs baseline: 1.0941x; 1.0941x over previous
#include <cuda_runtime.h>
#include <cstdint>

#define KK 64
#define BUFB 288   // padded u-buffer stride in bytes: 32 floats | 16B pad | 32 floats | 16B pad

__device__ __forceinline__ float fast_rcp(float x) {
    float r; asm("rcp.approx.f32 %0, %1;" : "=f"(r) : "f"(x)); return r;
}

__device__ __forceinline__ uint32_t smem_u32(const void* p) {
    uint32_t a;
    asm("{ .reg .u64 t; cvta.to.shared.u64 t, %1; cvt.u32.u64 %0, t; }"
        : "=r"(a) : "l"(p));
    return a;
}

// ONE BLOCK (2 warps, 64 threads) PER BATCH — R12 half-u split kept intact
// (interleaved chunk-load -> FMA, 2+2 accumulators; ptxas owns scheduling).
// Deltas vs R12: (a) y labels ride an 8-deep register pipeline so no y LDS
// gates the commit select; (b) partner FMAs/tree issue first so the
// shfl.xor(16) latency overlaps the own-output reduction.
//   u_t = (u_{t-1} . M) * exp(emit_t)        (masked steps: u_t = u_{t-1})
//   every 8th step (unconditional): u *= 1/u[0], C += log(u[0])
//   log_Z = C + log(sum_j u_T[j])
__global__ __launch_bounds__(KK, 1) void crf_forward_kernel(
    const int* __restrict__ y, const float* __restrict__ em,
    const float* __restrict__ tr, int Tn, float negInvB,
    float* __restrict__ out)
{
    __shared__ __align__(128) float u_sh[2][BUFB / 4]; // [buf][padded states]
    __shared__ int y_sh[1024];                         // T = 1024
    __shared__ float red2[2];

    const int tid = threadIdx.x;
    const int w = tid >> 5;               // warp
    const int l = tid & 31;               // lane
    const int h = (l >> 4) & 1;           // which u-half this thread loads
    const int so = 2 * l + w;             // own output state
    const int sp = 2 * (l ^ 16) + w;      // partner's output state
    const int b = blockIdx.x;
    const int* yb = y + (size_t)b * Tn;
    const float* eb = em + (size_t)b * Tn * KK;

    // padded float index for state s: halves 16B apart
    auto pidx = [](int s) { return s + ((s >= 32) ? 4 : 0); };

    // M pairs over MY half of rows, for my output and my partner's output:
    //   MpO[k] = (exp(tr[32h+2k][so]), exp(tr[32h+2k+1][so])), k = 0..15
    unsigned long long MpO[16], MpP[16];
#pragma unroll
    for (int k = 0; k < 16; k++) {
        const int r0 = (32 * h + 2 * k) * KK;
        float o0 = __expf(tr[r0 + so]);
        float o1 = __expf(tr[r0 + KK + so]);
        float p0 = __expf(tr[r0 + sp]);
        float p1 = __expf(tr[r0 + KK + sp]);
        asm("mov.b64 %0, {%1, %2};" : "=l"(MpO[k]) : "f"(o0), "f"(o1));
        asm("mov.b64 %0, {%1, %2};" : "=l"(MpP[k]) : "f"(p0), "f"(p1));
    }

    // stage y row in shared (cooperative)
    for (int t = tid; t < Tn; t += KK) y_sh[t] = yb[t];

    // u0 = exp(emissions[b,0,:]); own value kept in a register too
    float uown = __expf(eb[so]);
    u_sh[0][pidx(so)] = uown;
    float C = 0.f;
    __syncthreads();

    const uint32_t ubase = smem_u32(&u_sh[0][0]);
    const uint32_t uld0  = ubase + (uint32_t)(h * 144);      // my half base
    const uint32_t ust   = ubase + (uint32_t)(pidx(so) << 2);
    const float* ep = eb + so;

    // One recursion step. PSRC/RESC compile-time in the hot loop.
    // Shared loads/stores are asm volatile: prevents cross-step CSE of the
    // textually-identical unrolled bodies (the R4/R5 bug) and pins ordering.
    auto step = [&](float ecur, int yt, int psrc, bool resc) {
        float ex = __expf(ecur);
        float sc = 1.f;
        if (resc) {                       // unconditional rescale (valid always)
            float x0;
            asm volatile("ld.shared.f32 %0, [%1];"
                         : "=f"(x0) : "r"(ubase + (uint32_t)(psrc * BUFB)));
            sc = fast_rcp(x0);
            C += __logf(x0);
        }
        const float k = ex * sc;          // off the u-dependency chain
        const uint32_t ua = uld0 + (uint32_t)(psrc * BUFB);
        unsigned long long A0 = 0, A1 = 0, B0 = 0, B1 = 0;
#pragma unroll
        for (int i = 0; i < 8; i++) {     // my 32 u values, 4 per chunk
            unsigned long long q0, q1;    // (u[.4i],u[.4i+1]), (u[.4i+2],u[.4i+3])
            asm volatile("ld.shared.v2.u64 {%0, %1}, [%2];"
                : "=l"(q0), "=l"(q1) : "r"(ua + i * 16));
            // partner first: its reduction + shfl can start earliest
            asm("fma.rn.f32x2 %0, %1, %2, %0;" : "+l"(B0) : "l"(q0), "l"(MpP[2 * i]));
            asm("fma.rn.f32x2 %0, %1, %2, %0;" : "+l"(B1) : "l"(q1), "l"(MpP[2 * i + 1]));
            asm("fma.rn.f32x2 %0, %1, %2, %0;" : "+l"(A0) : "l"(q0), "l"(MpO[2 * i]));
            asm("fma.rn.f32x2 %0, %1, %2, %0;" : "+l"(A1) : "l"(q1), "l"(MpO[2 * i + 1]));
        }
        // partner tree -> shfl issues before own tree; shfl latency overlaps it
        asm("add.rn.f32x2 %0, %0, %1;" : "+l"(B0) : "l"(B1));
        float blo, bhi;
        asm("mov.b64 {%0, %1}, %2;" : "=f"(blo), "=f"(bhi) : "l"(B0));
        float PB = blo + bhi;                               // my half, partner's out
        float PBr = __shfl_xor_sync(0xffffffffu, PB, 16);   // other half, my out

        asm("add.rn.f32x2 %0, %0, %1;" : "+l"(A0) : "l"(A1));
        float alo, ahi;
        asm("mov.b64 {%0, %1}, %2;" : "=f"(alo), "=f"(ahi) : "l"(A0));
        float PA = alo + ahi;                               // my half, my out

        float dx = (PA + PBr) * k;
        // branchless commit (no BSSY/BSYNC in the hot loop)
        uown = (yt != 0) ? dx : uown * sc;
        asm volatile("st.shared.f32 [%0], %1;"
                     :: "r"(ust + (uint32_t)((psrc ^ 1) * BUFB)), "f"(uown));
        __syncthreads();
    };

    const int lim = Tn - 1;               // 1023
    auto eld = [&](int t) { return ep[(size_t)t * KK]; };

    // prefetch rows t .. t+7 (emissions AND y labels; no clamps: lim >= 8)
    float e0 = eld(1), e1 = eld(2), e2 = eld(3), e3 = eld(4);
    float e4 = eld(5), e5 = eld(6), e6 = eld(7), e7 = eld(8);
    int   y0 = y_sh[1], y1 = y_sh[2], y2 = y_sh[3], y3 = y_sh[4];
    int   y4 = y_sh[5], y5 = y_sh[6], y6 = y_sh[7], y7 = y_sh[8];

    int t = 1;
    // main loop: t ≡ 1 (mod 8); parity at entry always 0; rescale at t+7 (≡0 mod 8)
    for (; t + 15 <= lim; t += 8) {
        float n0 = eld(t + 8),  n1 = eld(t + 9),  n2 = eld(t + 10), n3 = eld(t + 11);
        float n4 = eld(t + 12), n5 = eld(t + 13), n6 = eld(t + 14), n7 = eld(t + 15);
        int   m0 = y_sh[t + 8],  m1 = y_sh[t + 9],  m2 = y_sh[t + 10], m3 = y_sh[t + 11];
        int   m4 = y_sh[t + 12], m5 = y_sh[t + 13], m6 = y_sh[t + 14], m7 = y_sh[t + 15];
        step(e0, y0, 0, false);
        step(e1, y1, 1, false);
        step(e2, y2, 0, false);
        step(e3, y3, 1, false);
        step(e4, y4, 0, false);
        step(e5, y5, 1, false);
        step(e6, y6, 0, false);
        step(e7, y7, 1, true);
        e0 = n0; e1 = n1; e2 = n2; e3 = n3;
        e4 = n4; e5 = n5; e6 = n6; e7 = n7;
        y0 = m0; y1 = m1; y2 = m2; y3 = m3;
        y4 = m4; y5 = m5; y6 = m6; y7 = m7;
    }

    // tail: runtime parity / rescale; shift-register prefetch with clamped loads
    int p = 0;                             // (t-1) is a multiple of 8 here
    for (; t <= lim; t++) {
        float nn = eld(min(t + 8, lim));
        int   mm = y_sh[min(t + 8, lim)];
        step(e0, y0, p, (t & 7) == 0);
        p ^= 1;
        e0 = e1; e1 = e2; e2 = e3; e3 = e4;
        e4 = e5; e5 = e6; e6 = e7; e7 = nn;
        y0 = y1; y1 = y2; y2 = y3; y3 = y4;
        y4 = y5; y5 = y6; y6 = y7; y7 = mm;
    }
    // final buffer parity: lim steps total from parity 0
    const int pf = lim & 1;

    // (last step ended with __syncthreads; u_sh[pf] is visible)

    // log_Z = C + log(sum u)   (redundant per-thread; identical result)
    float ssum = 0.f;
    {
        const float* up = &u_sh[pf][0];
#pragma unroll
        for (int c = 0; c < 16; c++) {
            const int fi = 4 * c + ((c >= 8) ? 4 : 0);   // padded layout
            float4 uu = *reinterpret_cast<const float4*>(up + fi);
            ssum += (uu.x + uu.y) + (uu.z + uu.w);
        }
    }
    float logz = C + __logf(ssum);

    // numerator: emission + transition scores along the gold path (masked)
    float num = 0.f;
    for (int tt = tid; tt < Tn; tt += KK) {
        int yt = y_sh[tt];
        if (yt != 0) {
            num += eb[(size_t)tt * KK + yt];
            if (tt > 0) num += tr[y_sh[tt - 1] * KK + yt];
        }
    }
#pragma unroll
    for (int o = 16; o > 0; o >>= 1) num += __shfl_xor_sync(0xffffffffu, num, o);
    if (l == 0) red2[w] = num;
    __syncthreads();
    if (tid == 0) {
        float ll = (red2[0] + red2[1]) - logz;
        atomicAdd(out, ll * negInvB);      // out pre-zeroed via memsetAsync
    }
}

extern "C" void kernel_launch(void* const* d_in, const int* in_sizes, int n_in,
                              void* d_out, int out_size)
{
    const int*   y  = (const int*)d_in[0];
    const float* em = (const float*)d_in[1];
    const float* tr = (const float*)d_in[2];

    const int Tn = 1024;                 // problem shape: B=256, T=1024, K=64
    const int B  = in_sizes[0] / Tn;

    cudaMemsetAsync(d_out, 0, sizeof(float));
    crf_forward_kernel<<<B, KK>>>(y, em, tr, Tn, -1.0f / (float)B,
                                  (float*)d_out);
}

// round 15
// speedup vs baseline: 1.2040x; 1.1004x over previous
#include <cuda_runtime.h>
#include <cstdint>

#define KK 64
#define BUFB 288   // padded u-buffer stride in bytes: 32 floats | 16B pad | 32 floats | 16B pad

__device__ __forceinline__ float fast_rcp(float x) {
    float r; asm("rcp.approx.f32 %0, %1;" : "=f"(r) : "f"(x)); return r;
}

__device__ __forceinline__ uint32_t smem_u32(const void* p) {
    uint32_t a;
    asm("{ .reg .u64 t; cvta.to.shared.u64 t, %1; cvt.u32.u64 %0, t; }"
        : "=r"(a) : "l"(p));
    return a;
}

// ONE BLOCK (2 warps, 64 threads) PER BATCH — exact R12 champion body with a
// single delta: the final reduction computes the PARTNER sum first so the
// shfl.xor(16) issues ~26 cycles earlier and its latency overlaps the own-
// output tree + k-multiply (critical-path shortening, not issue reduction).
//   u_t = (u_{t-1} . M) * exp(emit_t)        (masked steps: u_t = u_{t-1})
//   every 8th step (unconditional): u *= 1/u[0], C += log(u[0])
//   log_Z = C + log(sum_j u_T[j])
__global__ __launch_bounds__(KK, 1) void crf_forward_kernel(
    const int* __restrict__ y, const float* __restrict__ em,
    const float* __restrict__ tr, int Tn, float negInvB,
    float* __restrict__ out)
{
    __shared__ __align__(128) float u_sh[2][BUFB / 4]; // [buf][padded states]
    __shared__ int y_sh[1024];                         // T = 1024
    __shared__ float red2[2];

    const int tid = threadIdx.x;
    const int w = tid >> 5;               // warp
    const int l = tid & 31;               // lane
    const int h = (l >> 4) & 1;           // which u-half this thread loads
    const int so = 2 * l + w;             // own output state
    const int sp = 2 * (l ^ 16) + w;      // partner's output state
    const int b = blockIdx.x;
    const int* yb = y + (size_t)b * Tn;
    const float* eb = em + (size_t)b * Tn * KK;

    // padded float index for state s: halves 16B apart
    auto pidx = [](int s) { return s + ((s >= 32) ? 4 : 0); };

    // M pairs over MY half of rows, for my output and my partner's output:
    //   MpO[k] = (exp(tr[32h+2k][so]), exp(tr[32h+2k+1][so])), k = 0..15
    unsigned long long MpO[16], MpP[16];
#pragma unroll
    for (int k = 0; k < 16; k++) {
        const int r0 = (32 * h + 2 * k) * KK;
        float o0 = __expf(tr[r0 + so]);
        float o1 = __expf(tr[r0 + KK + so]);
        float p0 = __expf(tr[r0 + sp]);
        float p1 = __expf(tr[r0 + KK + sp]);
        asm("mov.b64 %0, {%1, %2};" : "=l"(MpO[k]) : "f"(o0), "f"(o1));
        asm("mov.b64 %0, {%1, %2};" : "=l"(MpP[k]) : "f"(p0), "f"(p1));
    }

    // stage y row in shared (cooperative)
    for (int t = tid; t < Tn; t += KK) y_sh[t] = yb[t];

    // u0 = exp(emissions[b,0,:]); own value kept in a register too
    float uown = __expf(eb[so]);
    u_sh[0][pidx(so)] = uown;
    float C = 0.f;
    __syncthreads();

    const uint32_t ubase = smem_u32(&u_sh[0][0]);
    const uint32_t uld0  = ubase + (uint32_t)(h * 144);      // my half base
    const uint32_t ust   = ubase + (uint32_t)(pidx(so) << 2);
    const float* ep = eb + so;

    // One recursion step. PSRC/RESC compile-time in the hot loop.
    // Shared loads/stores are asm volatile: prevents cross-step CSE of the
    // textually-identical unrolled bodies (the R4/R5 bug) and pins ordering.
    auto step = [&](float ecur, int tt, int psrc, bool resc) {
        const int yt = y_sh[tt];
        float ex = __expf(ecur);
        float sc = 1.f;
        if (resc) {                       // unconditional rescale (valid always)
            float x0;
            asm volatile("ld.shared.f32 %0, [%1];"
                         : "=f"(x0) : "r"(ubase + (uint32_t)(psrc * BUFB)));
            sc = fast_rcp(x0);
            C += __logf(x0);
        }
        const float k = ex * sc;          // off the u-dependency chain
        const uint32_t ua = uld0 + (uint32_t)(psrc * BUFB);
        unsigned long long A0 = 0, A1 = 0, B0 = 0, B1 = 0;
#pragma unroll
        for (int i = 0; i < 8; i++) {     // my 32 u values, 4 per chunk
            unsigned long long q0, q1;    // (u[.4i],u[.4i+1]), (u[.4i+2],u[.4i+3])
            asm volatile("ld.shared.v2.u64 {%0, %1}, [%2];"
                : "=l"(q0), "=l"(q1) : "r"(ua + i * 16));
            asm("fma.rn.f32x2 %0, %1, %2, %0;" : "+l"(A0) : "l"(q0), "l"(MpO[2 * i]));
            asm("fma.rn.f32x2 %0, %1, %2, %0;" : "+l"(A1) : "l"(q1), "l"(MpO[2 * i + 1]));
            asm("fma.rn.f32x2 %0, %1, %2, %0;" : "+l"(B0) : "l"(q0), "l"(MpP[2 * i]));
            asm("fma.rn.f32x2 %0, %1, %2, %0;" : "+l"(B1) : "l"(q1), "l"(MpP[2 * i + 1]));
        }
        // DELTA vs R12: partner reduction + shfl FIRST, own tree under the
        // shfl's 26-cycle flight.
        asm("add.rn.f32x2 %0, %0, %1;" : "+l"(B0) : "l"(B1));
        float blo, bhi;
        asm("mov.b64 {%0, %1}, %2;" : "=f"(blo), "=f"(bhi) : "l"(B0));
        float PB = blo + bhi;                               // my half, partner's out
        float PBr = __shfl_xor_sync(0xffffffffu, PB, 16);   // other half, my out

        asm("add.rn.f32x2 %0, %0, %1;" : "+l"(A0) : "l"(A1));
        float alo, ahi;
        asm("mov.b64 {%0, %1}, %2;" : "=f"(alo), "=f"(ahi) : "l"(A0));
        float PA = (alo + ahi) * k;                         // overlap shfl flight

        float dx = fmaf(PBr, k, PA);
        // branchless commit (no BSSY/BSYNC in the hot loop)
        uown = (yt != 0) ? dx : uown * sc;
        asm volatile("st.shared.f32 [%0], %1;"
                     :: "r"(ust + (uint32_t)((psrc ^ 1) * BUFB)), "f"(uown));
        __syncthreads();
    };

    const int lim = Tn - 1;               // 1023
    auto eld = [&](int t) { return ep[(size_t)t * KK]; };

    // prefetch rows t .. t+7 (no clamps needed: lim >= 8 here)
    float e0 = eld(1), e1 = eld(2), e2 = eld(3), e3 = eld(4);
    float e4 = eld(5), e5 = eld(6), e6 = eld(7), e7 = eld(8);

    int t = 1;
    // main loop: t ≡ 1 (mod 8); parity at entry always 0; rescale at t+7 (≡0 mod 8)
    for (; t + 15 <= lim; t += 8) {
        float n0 = eld(t + 8),  n1 = eld(t + 9),  n2 = eld(t + 10), n3 = eld(t + 11);
        float n4 = eld(t + 12), n5 = eld(t + 13), n6 = eld(t + 14), n7 = eld(t + 15);
        step(e0, t,     0, false);
        step(e1, t + 1, 1, false);
        step(e2, t + 2, 0, false);
        step(e3, t + 3, 1, false);
        step(e4, t + 4, 0, false);
        step(e5, t + 5, 1, false);
        step(e6, t + 6, 0, false);
        step(e7, t + 7, 1, true);
        e0 = n0; e1 = n1; e2 = n2; e3 = n3;
        e4 = n4; e5 = n5; e6 = n6; e7 = n7;
    }

    // tail: runtime parity / rescale; shift-register prefetch with clamped loads
    int p = 0;                             // (t-1) is a multiple of 8 here
    for (; t <= lim; t++) {
        float nn = eld(min(t + 8, lim));
        step(e0, t, p, (t & 7) == 0);
        p ^= 1;
        e0 = e1; e1 = e2; e2 = e3; e3 = e4;
        e4 = e5; e5 = e6; e6 = e7; e7 = nn;
    }
    // final buffer parity: lim steps total from parity 0
    const int pf = lim & 1;

    // (last step ended with __syncthreads; u_sh[pf] is visible)

    // log_Z = C + log(sum u)   (redundant per-thread; identical result)
    float ssum = 0.f;
    {
        const float* up = &u_sh[pf][0];
#pragma unroll
        for (int c = 0; c < 16; c++) {
            const int fi = 4 * c + ((c >= 8) ? 4 : 0);   // padded layout
            float4 uu = *reinterpret_cast<const float4*>(up + fi);
            ssum += (uu.x + uu.y) + (uu.z + uu.w);
        }
    }
    float logz = C + __logf(ssum);

    // numerator: emission + transition scores along the gold path (masked)
    float num = 0.f;
    for (int tt = tid; tt < Tn; tt += KK) {
        int yt = y_sh[tt];
        if (yt != 0) {
            num += eb[(size_t)tt * KK + yt];
            if (tt > 0) num += tr[y_sh[tt - 1] * KK + yt];
        }
    }
#pragma unroll
    for (int o = 16; o > 0; o >>= 1) num += __shfl_xor_sync(0xffffffffu, num, o);
    if (l == 0) red2[w] = num;
    __syncthreads();
    if (tid == 0) {
        float ll = (red2[0] + red2[1]) - logz;
        atomicAdd(out, ll * negInvB);      // out pre-zeroed via memsetAsync
    }
}

extern "C" void kernel_launch(void* const* d_in, const int* in_sizes, int n_in,
                              void* d_out, int out_size)
{
    const int*   y  = (const int*)d_in[0];
    const float* em = (const float*)d_in[1];
    const float* tr = (const float*)d_in[2];

    const int Tn = 1024;                 // problem shape: B=256, T=1024, K=64
    const int B  = in_sizes[0] / Tn;

    cudaMemsetAsync(d_out, 0, sizeof(float));
    crf_forward_kernel<<<B, KK>>>(y, em, tr, Tn, -1.0f / (float)B,
                                  (float*)d_out);
}